// round 4
// baseline (speedup 1.0000x reference)
#include <cuda_runtime.h>
#include <cstdint>

#define NPTS   65536
#define NQ     1024
#define NBATCH 2
#define NS1    32
#define NS2    64
#define NOUT   128
#define CAP    16384                // phase-1 scan cap
#define SEG    ((NPTS - CAP) / 8)   // 6144 points per phase-2 warp
#define STAGE  1024                 // points per latency-batched stage
#define VG     (STAGE / 32)         // 32 float4 loads per lane per stage

static __device__ float4 g_pts4[NBATCH * NPTS];          // (x,y,z,|p|^2)
static __device__ int    g_lists[NBATCH * NQ * 96];      // [l1(32)|l2(64)] per query
static __device__ int    g_state[NBATCH * NQ * 2];       // capped cnt1, cnt2

__device__ __forceinline__ float sq3_rn(float x, float y, float z) {
    return __fadd_rn(__fadd_rn(__fmul_rn(x, x), __fmul_rn(y, y)), __fmul_rn(z, z));
}

__device__ __forceinline__ int query_flat_index(int q, int& b) {
    b = q >> 10;
    const int m = q & 1023;
    return (4 + 8 * (m >> 5)) * 256 + (4 + 8 * (m & 31));
}

__device__ __forceinline__ void radii(float& r1sq, float& r2sq) {
    r1sq = __fmul_rn(0.1f, 0.1f);
    r2sq = __fmul_rn(0.2f, 0.2f);
}

// Evaluate one 32-point group from preloaded registers; ordered append.
__device__ __forceinline__ void eval_group(
    float4 pt, float qx, float qy, float qz, float q2,
    float r1sq, float r2sq, int idx, unsigned lt,
    int& cnt1, int& cnt2, int* __restrict__ l1, int* __restrict__ l2)
{
    const float dot = __fadd_rn(__fadd_rn(__fmul_rn(pt.x, qx), __fmul_rn(pt.y, qy)),
                                __fmul_rn(pt.z, qz));
    const float d2  = __fadd_rn(__fadd_rn(q2, pt.w), __fmul_rn(-2.0f, dot));
    const bool h2 = d2 < r2sq;
    const unsigned m2 = __ballot_sync(0xffffffffu, h2);
    if (m2) {
        const bool h1 = d2 < r1sq;
        const unsigned m1 = __ballot_sync(0xffffffffu, h1);
        if (h1) { const int p = cnt1 + __popc(m1 & lt); if (p < NS1) l1[p] = idx; }
        if (h2) { const int p = cnt2 + __popc(m2 & lt); if (p < NS2) l2[p] = idx; }
        cnt1 += __popc(m1);
        cnt2 += __popc(m2);
    }
}

// One 1024-point stage: all 32 LDG.128 issued before any eval (single exposed
// L2 latency per stage — addresses never depend on scan state).
__device__ __forceinline__ void scan_stage(
    const float4* __restrict__ P4, int base, int lane,
    float qx, float qy, float qz, float q2, float r1sq, float r2sq, unsigned lt,
    int& cnt1, int& cnt2, int* __restrict__ l1, int* __restrict__ l2)
{
    float4 v[VG];
#pragma unroll
    for (int j = 0; j < VG; j++) v[j] = __ldg(P4 + base + j * 32 + lane);
#pragma unroll
    for (int j = 0; j < VG; j++)
        eval_group(v[j], qx, qy, qz, q2, r1sq, r2sq, base + j * 32 + lane,
                   lt, cnt1, cnt2, l1, l2);
}

// ---------------------------------------------------------------------------
// Kernel 0: pack pts -> float4(x,y,z,|p|^2)
// ---------------------------------------------------------------------------
__global__ __launch_bounds__(256) void pack_kernel(const float* __restrict__ pts) {
    const int i = blockIdx.x * 256 + threadIdx.x;   // 0 .. 131071
    const float x = __ldg(pts + 3 * i + 0);
    const float y = __ldg(pts + 3 * i + 1);
    const float z = __ldg(pts + 3 * i + 2);
    g_pts4[i] = make_float4(x, y, z, sq3_rn(x, y, z));
}

// ---------------------------------------------------------------------------
// Kernel 1: phase-1 scan. One independent warp per query, first CAP points,
// latency-batched 1024-point stages, early exit when both lists full.
// ---------------------------------------------------------------------------
__global__ __launch_bounds__(256) void scan1_kernel() {
    __shared__ int s_l[8][96];

    const int lane = threadIdx.x & 31;
    const int wid  = threadIdx.x >> 5;
    const int q    = blockIdx.x * 8 + wid;          // 0..2047
    int b;
    const int fi = query_flat_index(q, b);

    const float4* __restrict__ P4 = g_pts4 + (size_t)b * NPTS;
    const float4 qp = __ldg(P4 + fi);
    const float qx = qp.x, qy = qp.y, qz = qp.z, q2 = qp.w;
    float r1sq, r2sq; radii(r1sq, r2sq);

    int* l1 = s_l[wid];
    int* l2 = s_l[wid] + NS1;
    int cnt1 = 0, cnt2 = 0;
    const unsigned lt = (1u << lane) - 1u;

    for (int base = 0; base < CAP; base += STAGE) {
        scan_stage(P4, base, lane, qx, qy, qz, q2, r1sq, r2sq, lt, cnt1, cnt2, l1, l2);
        if (cnt1 >= NS1 && cnt2 >= NS2) break;
    }
    __syncwarp();

    if (lane == 0) {
        g_state[q * 2 + 0] = min(cnt1, NS1);
        g_state[q * 2 + 1] = min(cnt2, NS2);
    }
    int* dst = g_lists + q * 96;
    for (int j = lane; j < 96; j += 32) dst[j] = s_l[wid][j];
}

// ---------------------------------------------------------------------------
// Kernel 2: phase-2 tail. One block (8 warps) per undone query; remaining
// points split into 8 contiguous segments scanned in parallel with the same
// latency-batched stages; per-segment ordered lists merged by prefix offsets.
// ---------------------------------------------------------------------------
__global__ __launch_bounds__(256) void scan2_kernel() {
    const int q = blockIdx.x;
    const int cnt1 = g_state[q * 2 + 0];
    const int cnt2 = g_state[q * 2 + 1];
    if (cnt1 >= NS1 && cnt2 >= NS2) return;

    __shared__ int lc1[8], lc2[8];
    __shared__ int ll1[8][NS1];
    __shared__ int ll2[8][NS2];

    const int lane = threadIdx.x & 31;
    const int wid  = threadIdx.x >> 5;
    int b;
    const int fi = query_flat_index(q, b);

    const float4* __restrict__ P4 = g_pts4 + (size_t)b * NPTS;
    const float4 qp = __ldg(P4 + fi);
    const float qx = qp.x, qy = qp.y, qz = qp.z, q2 = qp.w;
    float r1sq, r2sq; radii(r1sq, r2sq);

    int c1 = 0, c2 = 0;
    const unsigned lt = (1u << lane) - 1u;
    const int seg0 = CAP + wid * SEG;

    for (int base = seg0; base < seg0 + SEG; base += STAGE) {
        scan_stage(P4, base, lane, qx, qy, qz, q2, r1sq, r2sq, lt, c1, c2, ll1[wid], ll2[wid]);
        if (c1 >= NS1 && c2 >= NS2) break;
    }
    if (lane == 0) { lc1[wid] = min(c1, NS1); lc2[wid] = min(c2, NS2); }
    __syncthreads();

    int off1 = cnt1, off2 = cnt2;
#pragma unroll
    for (int v = 0; v < 8; v++) {
        if (v < wid) { off1 += lc1[v]; off2 += lc2[v]; }
    }
    const int n1 = lc1[wid], n2 = lc2[wid];
    int* g1 = g_lists + q * 96;
    int* g2 = g1 + NS1;
    for (int j = lane; j < n1; j += 32) { const int p = off1 + j; if (p < NS1) g1[p] = ll1[wid][j]; }
    for (int j = lane; j < n2; j += 32) { const int p = off2 + j; if (p < NS2) g2[p] = ll2[wid][j]; }
    __syncthreads();

    int t1 = cnt1, t2 = cnt2;
#pragma unroll
    for (int v = 0; v < 8; v++) { t1 += lc1[v]; t2 += lc2[v]; }
    t1 = min(t1, NS1); t2 = min(t2, NS2);

    if (wid == 0) {           // pad list1 with first element (or 0 if empty)
        const int f1 = (t1 > 0) ? g1[0] : 0;
        for (int j = t1 + lane; j < NS1; j += 32) g1[j] = f1;
    } else if (wid == 1) {    // pad list2
        const int f2 = (t2 > 0) ? g2[0] : 0;
        for (int j = t2 + lane; j < NS2; j += 32) g2[j] = f2;
    }
}

// ---------------------------------------------------------------------------
// Kernel 3: MLP. 8 queries per 256-thread block (256 blocks ~ 2/SM).
// ---------------------------------------------------------------------------
#define INVC 0.9999950000374997f

__device__ __forceinline__ void mlp_point(
    float gx, float gy, float gz, float qx, float qy, float qz,
    const float* __restrict__ sA, const float* __restrict__ scA, const float* __restrict__ biA,
    const float* __restrict__ sB, const float* __restrict__ scB, const float* __restrict__ biB,
    float f[32])
{
    const float x0 = gx - qx, x1 = gy - qy, x2 = gz - qz;
    float a[16];
#pragma unroll
    for (int o = 0; o < 16; o++) {
        const float* w = sA + o * 6;
        float y = x0 * w[0];
        y = fmaf(x1, w[1], y);
        y = fmaf(x2, w[2], y);
        y = fmaf(gx, w[3], y);
        y = fmaf(gy, w[4], y);
        y = fmaf(gz, w[5], y);
        a[o] = fmaxf(fmaf(y, scA[o], biA[o]), 0.0f);
    }
#pragma unroll
    for (int o = 0; o < 32; o++) {
        const float* w = sB + o * 16;
        float y = 0.0f;
#pragma unroll
        for (int c = 0; c < 16; c++) y = fmaf(a[c], w[c], y);
        f[o] = fmaxf(f[o], fmaxf(fmaf(y, scB[o], biB[o]), 0.0f));
    }
}

__device__ __forceinline__ void warp_max32(float f[32]) {
#pragma unroll
    for (int o = 0; o < 32; o++) {
        float v = f[o];
        v = fmaxf(v, __shfl_xor_sync(0xffffffffu, v, 16));
        v = fmaxf(v, __shfl_xor_sync(0xffffffffu, v, 8));
        v = fmaxf(v, __shfl_xor_sync(0xffffffffu, v, 4));
        v = fmaxf(v, __shfl_xor_sync(0xffffffffu, v, 2));
        v = fmaxf(v, __shfl_xor_sync(0xffffffffu, v, 1));
        f[o] = v;
    }
}

__global__ __launch_bounds__(256) void mlp_kernel(
    const float* __restrict__ w1a, const float* __restrict__ g1a, const float* __restrict__ b1a,
    const float* __restrict__ w1b, const float* __restrict__ g1b, const float* __restrict__ b1b,
    const float* __restrict__ w2a, const float* __restrict__ g2a, const float* __restrict__ b2a,
    const float* __restrict__ w2b, const float* __restrict__ g2b, const float* __restrict__ b2b,
    const float* __restrict__ w3,  const float* __restrict__ b3,
    float* __restrict__ out)
{
    __shared__ float s_w1a[96],  s_w2a[96];
    __shared__ float s_w1b[512], s_w2b[512];
    __shared__ float s_sc1a[16], s_bi1a[16], s_sc2a[16], s_bi2a[16];
    __shared__ float s_sc1b[32], s_bi1b[32], s_sc2b[32], s_bi2b[32];
    __shared__ float s_w3t[64 * 129];   // transposed + padded

    const int tid = threadIdx.x;
    for (int i = tid; i < 96; i += 256)  { s_w1a[i] = w1a[i]; s_w2a[i] = w2a[i]; }
    for (int i = tid; i < 512; i += 256) { s_w1b[i] = w1b[i]; s_w2b[i] = w2b[i]; }
    if (tid < 16) {
        s_sc1a[tid] = g1a[tid] * INVC; s_bi1a[tid] = b1a[tid];
        s_sc2a[tid] = g2a[tid] * INVC; s_bi2a[tid] = b2a[tid];
    } else if (tid < 48) {
        const int i = tid - 16;
        s_sc1b[i] = g1b[i] * INVC; s_bi1b[i] = b1b[i];
        s_sc2b[i] = g2b[i] * INVC; s_bi2b[i] = b2b[i];
    }
    const float4* __restrict__ w3v = (const float4*)w3;
    for (int i = tid; i < NOUT * 16; i += 256) {
        const float4 v = __ldg(w3v + i);
        const int o  = i >> 4;
        const int c4 = (i & 15) * 4;
        s_w3t[(c4 + 0) * 129 + o] = v.x;
        s_w3t[(c4 + 1) * 129 + o] = v.y;
        s_w3t[(c4 + 2) * 129 + o] = v.z;
        s_w3t[(c4 + 3) * 129 + o] = v.w;
    }
    __syncthreads();

    const int lane = tid & 31;
    const int wid  = tid >> 5;
    const int q    = blockIdx.x * 8 + wid;          // 256 blocks x 8 queries
    int b;
    const int fi = query_flat_index(q, b);

    const float4* __restrict__ P4 = g_pts4 + (size_t)b * NPTS;
    const float4 qp = __ldg(P4 + fi);
    const float qx = qp.x, qy = qp.y, qz = qp.z;

    const int* lst = g_lists + q * 96;
    const int i0 = __ldg(lst + lane);
    const int i1 = __ldg(lst + NS1 + lane);
    const int i2 = __ldg(lst + NS1 + 32 + lane);
    const float4 n0 = __ldg(P4 + i0);
    const float4 n1 = __ldg(P4 + i1);
    const float4 n2 = __ldg(P4 + i2);

    const size_t ob = (size_t)q * NOUT;
    float acc[4];
#pragma unroll
    for (int k = 0; k < 4; k++) acc[k] = __ldg(b3 + lane + 32 * k);

    {   // branch 1 (S=32)
        float f[32];
#pragma unroll
        for (int o = 0; o < 32; o++) f[o] = 0.0f;
        mlp_point(n0.x, n0.y, n0.z, qx, qy, qz, s_w1a, s_sc1a, s_bi1a, s_w1b, s_sc1b, s_bi1b, f);
        warp_max32(f);
#pragma unroll
        for (int k = 0; k < 4; k++) {
            const int o = lane + 32 * k;
            float a = acc[k];
#pragma unroll
            for (int c = 0; c < 32; c++) a = fmaf(f[c], s_w3t[c * 129 + o], a);
            acc[k] = a;
        }
    }
    {   // branch 2 (S=64)
        float f[32];
#pragma unroll
        for (int o = 0; o < 32; o++) f[o] = 0.0f;
        mlp_point(n1.x, n1.y, n1.z, qx, qy, qz, s_w2a, s_sc2a, s_bi2a, s_w2b, s_sc2b, s_bi2b, f);
        mlp_point(n2.x, n2.y, n2.z, qx, qy, qz, s_w2a, s_sc2a, s_bi2a, s_w2b, s_sc2b, s_bi2b, f);
        warp_max32(f);
#pragma unroll
        for (int k = 0; k < 4; k++) {
            const int o = lane + 32 * k;
            float a = acc[k];
#pragma unroll
            for (int c = 0; c < 32; c++) a = fmaf(f[c], s_w3t[(c + 32) * 129 + o], a);
            acc[k] = a;
        }
    }
#pragma unroll
    for (int k = 0; k < 4; k++) out[ob + lane + 32 * k] = acc[k];
}

extern "C" void kernel_launch(void* const* d_in, const int* in_sizes, int n_in,
                              void* d_out, int out_size) {
    const float* pts = (const float*)d_in[0];
    const float* w1a = (const float*)d_in[1];
    const float* g1a = (const float*)d_in[2];
    const float* b1a = (const float*)d_in[3];
    const float* w1b = (const float*)d_in[4];
    const float* g1b = (const float*)d_in[5];
    const float* b1b = (const float*)d_in[6];
    const float* w2a = (const float*)d_in[7];
    const float* g2a = (const float*)d_in[8];
    const float* b2a = (const float*)d_in[9];
    const float* w2b = (const float*)d_in[10];
    const float* g2b = (const float*)d_in[11];
    const float* b2b = (const float*)d_in[12];
    const float* w3  = (const float*)d_in[13];
    const float* b3  = (const float*)d_in[14];
    float* out = (float*)d_out;

    pack_kernel<<<NBATCH * NPTS / 256, 256>>>(pts);
    scan1_kernel<<<NBATCH * NQ / 8, 256>>>();
    scan2_kernel<<<NBATCH * NQ, 256>>>();
    mlp_kernel<<<NBATCH * NQ / 8, 256>>>(w1a, g1a, b1a, w1b, g1b, b1b,
                                         w2a, g2a, b2a, w2b, g2b, b2b, w3, b3, out);
}

// round 5
// speedup vs baseline: 1.0118x; 1.0118x over previous
#include <cuda_runtime.h>
#include <cstdint>

#define NPTS   65536
#define NQ     1024
#define NBATCH 2
#define NS1    32
#define NS2    64
#define NOUT   128
#define CAP    32768                // phase-1 scan cap
#define SEG2   ((NPTS - CAP) / 8)   // 4096 points per phase-2 warp

static __device__ float4 g_pts4[NBATCH * NPTS];          // (x,y,z,|p|^2)
static __device__ float4 g_w3t4[64 * 32];                // [c][lane] -> 4 outputs o=lane+32k
static __device__ int    g_lists[NBATCH * NQ * 96];      // [l1(32)|l2(64)] per query
static __device__ int    g_state[NBATCH * NQ * 2];       // capped cnt1, cnt2

__device__ __forceinline__ float sq3_rn(float x, float y, float z) {
    return __fadd_rn(__fadd_rn(__fmul_rn(x, x), __fmul_rn(y, y)), __fmul_rn(z, z));
}

__device__ __forceinline__ int query_flat_index(int q, int& b) {
    b = q >> 10;
    const int m = q & 1023;
    return (4 + 8 * (m >> 5)) * 256 + (4 + 8 * (m & 31));
}

__device__ __forceinline__ void radii(float& r1sq, float& r2sq) {
    r1sq = __fmul_rn(0.1f, 0.1f);
    r2sq = __fmul_rn(0.2f, 0.2f);
}

// Branchless dual-list eval: 2 ballots, predicated appends, no divergent branch.
__device__ __forceinline__ void eval_both(
    float4 pt, float qx, float qy, float qz, float q2,
    float r1sq, float r2sq, int idx, unsigned lt,
    int& cnt1, int& cnt2, int* __restrict__ l1, int* __restrict__ l2)
{
    const float dot = __fadd_rn(__fadd_rn(__fmul_rn(pt.x, qx), __fmul_rn(pt.y, qy)),
                                __fmul_rn(pt.z, qz));
    const float d2  = __fadd_rn(__fadd_rn(q2, pt.w), __fmul_rn(-2.0f, dot));
    const bool h1 = d2 < r1sq;
    const bool h2 = d2 < r2sq;
    const unsigned m1 = __ballot_sync(0xffffffffu, h1);
    const unsigned m2 = __ballot_sync(0xffffffffu, h2);
    const int p1 = cnt1 + __popc(m1 & lt);
    const int p2 = cnt2 + __popc(m2 & lt);
    if (h1 & (p1 < NS1)) l1[p1] = idx;
    if (h2 & (p2 < NS2)) l2[p2] = idx;
    cnt1 += __popc(m1);
    cnt2 += __popc(m2);
}

// Branchless single-list eval (list1 only; used after list2 is full).
__device__ __forceinline__ void eval_one(
    float4 pt, float qx, float qy, float qz, float q2,
    float r1sq, int idx, unsigned lt,
    int& cnt1, int* __restrict__ l1)
{
    const float dot = __fadd_rn(__fadd_rn(__fmul_rn(pt.x, qx), __fmul_rn(pt.y, qy)),
                                __fmul_rn(pt.z, qz));
    const float d2  = __fadd_rn(__fadd_rn(q2, pt.w), __fmul_rn(-2.0f, dot));
    const bool h1 = d2 < r1sq;
    const unsigned m1 = __ballot_sync(0xffffffffu, h1);
    const int p1 = cnt1 + __popc(m1 & lt);
    if (h1 & (p1 < NS1)) l1[p1] = idx;
    cnt1 += __popc(m1);
}

// ---------------------------------------------------------------------------
// Kernel 0: pack pts -> float4(x,y,z,|p|^2), and pack w3 -> g_w3t4.
// ---------------------------------------------------------------------------
__global__ __launch_bounds__(256) void prep_kernel(const float* __restrict__ pts,
                                                   const float* __restrict__ w3) {
    const int blk = blockIdx.x;
    if (blk < NBATCH * NPTS / 256) {
        const int i = blk * 256 + threadIdx.x;
        const float x = __ldg(pts + 3 * i + 0);
        const float y = __ldg(pts + 3 * i + 1);
        const float z = __ldg(pts + 3 * i + 2);
        g_pts4[i] = make_float4(x, y, z, sq3_rn(x, y, z));
    } else {
        const int i = (blk - NBATCH * NPTS / 256) * 256 + threadIdx.x;  // 0..2047
        if (i < 64 * 32) {
            const int c = i >> 5, j = i & 31;
            g_w3t4[i] = make_float4(__ldg(w3 + (j +  0) * 64 + c),
                                    __ldg(w3 + (j + 32) * 64 + c),
                                    __ldg(w3 + (j + 64) * 64 + c),
                                    __ldg(w3 + (j + 96) * 64 + c));
        }
    }
}

// ---------------------------------------------------------------------------
// Kernel 1: phase-1 scan. One warp per query, points [0, CAP), branchless
// eval, unroll 8 (32 regs, no spill), break check every 1024 points.
// All warps in a block walk the same addresses -> L1 reuse.
// ---------------------------------------------------------------------------
__global__ __launch_bounds__(256) void scan1_kernel() {
    __shared__ int s_l[8][96];

    const int lane = threadIdx.x & 31;
    const int wid  = threadIdx.x >> 5;
    const int q    = blockIdx.x * 8 + wid;          // 0..2047
    int b;
    const int fi = query_flat_index(q, b);

    const float4* __restrict__ P4 = g_pts4 + (size_t)b * NPTS;
    const float4 qp = __ldg(P4 + fi);
    const float qx = qp.x, qy = qp.y, qz = qp.z, q2 = qp.w;
    float r1sq, r2sq; radii(r1sq, r2sq);

    int* l1 = s_l[wid];
    int* l2 = s_l[wid] + NS1;
    int cnt1 = 0, cnt2 = 0;
    const unsigned lt = (1u << lane) - 1u;

    int base = 0;
    // Mode A: both lists active.
    while (base < CAP) {
#pragma unroll
        for (int c = 0; c < 1024; c += 256) {
            float4 v[8];
#pragma unroll
            for (int j = 0; j < 8; j++) v[j] = __ldg(P4 + base + c + j * 32 + lane);
#pragma unroll
            for (int j = 0; j < 8; j++)
                eval_both(v[j], qx, qy, qz, q2, r1sq, r2sq,
                          base + c + j * 32 + lane, lt, cnt1, cnt2, l1, l2);
        }
        base += 1024;
        if (cnt2 >= NS2) break;
    }
    // Mode B: list1 only.
    if (cnt1 < NS1) {
        while (base < CAP) {
#pragma unroll
            for (int c = 0; c < 1024; c += 256) {
                float4 v[8];
#pragma unroll
                for (int j = 0; j < 8; j++) v[j] = __ldg(P4 + base + c + j * 32 + lane);
#pragma unroll
                for (int j = 0; j < 8; j++)
                    eval_one(v[j], qx, qy, qz, q2, r1sq,
                             base + c + j * 32 + lane, lt, cnt1, l1);
            }
            base += 1024;
            if (cnt1 >= NS1) break;
        }
    }
    __syncwarp();

    if (lane == 0) {
        g_state[q * 2 + 0] = min(cnt1, NS1);
        g_state[q * 2 + 1] = min(cnt2, NS2);
    }
    int* dst = g_lists + q * 96;
    for (int j = lane; j < 96; j += 32) dst[j] = s_l[wid][j];
}

// ---------------------------------------------------------------------------
// Kernel 2: phase-2 tail. One block per undone query; points [CAP, NPTS)
// split into 8 contiguous segments scanned in parallel (branchless eval);
// ordered per-segment lists merged by prefix offsets.
// ---------------------------------------------------------------------------
__global__ __launch_bounds__(256) void scan2_kernel() {
    const int q = blockIdx.x;
    const int cnt1 = g_state[q * 2 + 0];
    const int cnt2 = g_state[q * 2 + 1];
    if (cnt1 >= NS1 && cnt2 >= NS2) return;

    __shared__ int lc1[8], lc2[8];
    __shared__ int ll1[8][NS1];
    __shared__ int ll2[8][NS2];

    const int lane = threadIdx.x & 31;
    const int wid  = threadIdx.x >> 5;
    int b;
    const int fi = query_flat_index(q, b);

    const float4* __restrict__ P4 = g_pts4 + (size_t)b * NPTS;
    const float4 qp = __ldg(P4 + fi);
    const float qx = qp.x, qy = qp.y, qz = qp.z, q2 = qp.w;
    float r1sq, r2sq; radii(r1sq, r2sq);

    int c1 = 0, c2 = 0;
    const unsigned lt = (1u << lane) - 1u;
    const int seg0 = CAP + wid * SEG2;

    for (int base = seg0; base < seg0 + SEG2; base += 1024) {
#pragma unroll
        for (int c = 0; c < 1024; c += 256) {
            float4 v[8];
#pragma unroll
            for (int j = 0; j < 8; j++) v[j] = __ldg(P4 + base + c + j * 32 + lane);
#pragma unroll
            for (int j = 0; j < 8; j++)
                eval_both(v[j], qx, qy, qz, q2, r1sq, r2sq,
                          base + c + j * 32 + lane, lt, c1, c2, ll1[wid], ll2[wid]);
        }
        if (c1 >= NS1 && c2 >= NS2) break;
    }
    if (lane == 0) { lc1[wid] = min(c1, NS1); lc2[wid] = min(c2, NS2); }
    __syncthreads();

    int off1 = cnt1, off2 = cnt2;
#pragma unroll
    for (int v = 0; v < 8; v++) {
        if (v < wid) { off1 += lc1[v]; off2 += lc2[v]; }
    }
    const int n1 = lc1[wid], n2 = lc2[wid];
    int* g1 = g_lists + q * 96;
    int* g2 = g1 + NS1;
    for (int j = lane; j < n1; j += 32) { const int p = off1 + j; if (p < NS1) g1[p] = ll1[wid][j]; }
    for (int j = lane; j < n2; j += 32) { const int p = off2 + j; if (p < NS2) g2[p] = ll2[wid][j]; }
    __syncthreads();

    int t1 = cnt1, t2 = cnt2;
#pragma unroll
    for (int v = 0; v < 8; v++) { t1 += lc1[v]; t2 += lc2[v]; }
    t1 = min(t1, NS1); t2 = min(t2, NS2);

    if (wid == 0) {
        const int f1 = (t1 > 0) ? g1[0] : 0;
        for (int j = t1 + lane; j < NS1; j += 32) g1[j] = f1;
    } else if (wid == 1) {
        const int f2 = (t2 > 0) ? g2[0] : 0;
        for (int j = t2 + lane; j < NS2; j += 32) g2[j] = f2;
    }
}

// ---------------------------------------------------------------------------
// Kernel 3: MLP. One warp per query, 8 per 256-thread block. Weight loads
// vectorized (float4); branch-2's two points share each weight load; w3
// consumed directly from pre-packed g_w3t4 via coalesced __ldg (no transpose
// preamble, no sync after tiny weight staging only).
// ---------------------------------------------------------------------------
#define INVC 0.9999950000374997f

// Layer A+B for ONE point (branch 1).
__device__ __forceinline__ void mlp_point1(
    float gx, float gy, float gz, float qx, float qy, float qz,
    const float4* __restrict__ wA,   // 16 rows x 8 floats (2 float4/row)
    const float* __restrict__ scA, const float* __restrict__ biA,
    const float4* __restrict__ wB,   // 32 rows x 16 floats (4 float4/row)
    const float* __restrict__ scB, const float* __restrict__ biB,
    float f[32])
{
    const float x0 = gx - qx, x1 = gy - qy, x2 = gz - qz;
    float a[16];
#pragma unroll
    for (int o = 0; o < 16; o++) {
        const float4 w0 = wA[o * 2 + 0];
        const float4 w1 = wA[o * 2 + 1];
        float y = x0 * w0.x;
        y = fmaf(x1, w0.y, y); y = fmaf(x2, w0.z, y);
        y = fmaf(gx, w0.w, y); y = fmaf(gy, w1.x, y); y = fmaf(gz, w1.y, y);
        a[o] = fmaxf(fmaf(y, scA[o], biA[o]), 0.0f);
    }
#pragma unroll
    for (int o = 0; o < 32; o++) {
        const float4 b0 = wB[o * 4 + 0], b1 = wB[o * 4 + 1];
        const float4 b2 = wB[o * 4 + 2], b3 = wB[o * 4 + 3];
        float y;
        y = a[0] * b0.x;           y = fmaf(a[1],  b0.y, y);
        y = fmaf(a[2],  b0.z, y);  y = fmaf(a[3],  b0.w, y);
        y = fmaf(a[4],  b1.x, y);  y = fmaf(a[5],  b1.y, y);
        y = fmaf(a[6],  b1.z, y);  y = fmaf(a[7],  b1.w, y);
        y = fmaf(a[8],  b2.x, y);  y = fmaf(a[9],  b2.y, y);
        y = fmaf(a[10], b2.z, y);  y = fmaf(a[11], b2.w, y);
        y = fmaf(a[12], b3.x, y);  y = fmaf(a[13], b3.y, y);
        y = fmaf(a[14], b3.z, y);  y = fmaf(a[15], b3.w, y);
        f[o] = fmaxf(f[o], fmaxf(fmaf(y, scB[o], biB[o]), 0.0f));
    }
}

// Layer A+B for TWO points sharing every weight load (branch 2).
__device__ __forceinline__ void mlp_point2(
    float g1x, float g1y, float g1z, float g2x, float g2y, float g2z,
    float qx, float qy, float qz,
    const float4* __restrict__ wA,
    const float* __restrict__ scA, const float* __restrict__ biA,
    const float4* __restrict__ wB,
    const float* __restrict__ scB, const float* __restrict__ biB,
    float f[32])
{
    const float u0 = g1x - qx, u1 = g1y - qy, u2 = g1z - qz;
    const float v0 = g2x - qx, v1 = g2y - qy, v2 = g2z - qz;
    float a[16], c[16];
#pragma unroll
    for (int o = 0; o < 16; o++) {
        const float4 w0 = wA[o * 2 + 0];
        const float4 w1 = wA[o * 2 + 1];
        float ya = u0 * w0.x;
        ya = fmaf(u1, w0.y, ya); ya = fmaf(u2, w0.z, ya);
        ya = fmaf(g1x, w0.w, ya); ya = fmaf(g1y, w1.x, ya); ya = fmaf(g1z, w1.y, ya);
        a[o] = fmaxf(fmaf(ya, scA[o], biA[o]), 0.0f);
        float yc = v0 * w0.x;
        yc = fmaf(v1, w0.y, yc); yc = fmaf(v2, w0.z, yc);
        yc = fmaf(g2x, w0.w, yc); yc = fmaf(g2y, w1.x, yc); yc = fmaf(g2z, w1.y, yc);
        c[o] = fmaxf(fmaf(yc, scA[o], biA[o]), 0.0f);
    }
#pragma unroll
    for (int o = 0; o < 32; o++) {
        const float4 b0 = wB[o * 4 + 0], b1 = wB[o * 4 + 1];
        const float4 b2 = wB[o * 4 + 2], b3 = wB[o * 4 + 3];
        float ya, yc;
        ya = a[0] * b0.x;          yc = c[0] * b0.x;
        ya = fmaf(a[1],  b0.y, ya); yc = fmaf(c[1],  b0.y, yc);
        ya = fmaf(a[2],  b0.z, ya); yc = fmaf(c[2],  b0.z, yc);
        ya = fmaf(a[3],  b0.w, ya); yc = fmaf(c[3],  b0.w, yc);
        ya = fmaf(a[4],  b1.x, ya); yc = fmaf(c[4],  b1.x, yc);
        ya = fmaf(a[5],  b1.y, ya); yc = fmaf(c[5],  b1.y, yc);
        ya = fmaf(a[6],  b1.z, ya); yc = fmaf(c[6],  b1.z, yc);
        ya = fmaf(a[7],  b1.w, ya); yc = fmaf(c[7],  b1.w, yc);
        ya = fmaf(a[8],  b2.x, ya); yc = fmaf(c[8],  b2.x, yc);
        ya = fmaf(a[9],  b2.y, ya); yc = fmaf(c[9],  b2.y, yc);
        ya = fmaf(a[10], b2.z, ya); yc = fmaf(c[10], b2.z, yc);
        ya = fmaf(a[11], b2.w, ya); yc = fmaf(c[11], b2.w, yc);
        ya = fmaf(a[12], b3.x, ya); yc = fmaf(c[12], b3.x, yc);
        ya = fmaf(a[13], b3.y, ya); yc = fmaf(c[13], b3.y, yc);
        ya = fmaf(a[14], b3.z, ya); yc = fmaf(c[14], b3.z, yc);
        ya = fmaf(a[15], b3.w, ya); yc = fmaf(c[15], b3.w, yc);
        const float ra = fmaxf(fmaf(ya, scB[o], biB[o]), 0.0f);
        const float rc = fmaxf(fmaf(yc, scB[o], biB[o]), 0.0f);
        f[o] = fmaxf(f[o], fmaxf(ra, rc));
    }
}

__device__ __forceinline__ void warp_max32(float f[32]) {
#pragma unroll
    for (int o = 0; o < 32; o++) {
        float v = f[o];
        v = fmaxf(v, __shfl_xor_sync(0xffffffffu, v, 16));
        v = fmaxf(v, __shfl_xor_sync(0xffffffffu, v, 8));
        v = fmaxf(v, __shfl_xor_sync(0xffffffffu, v, 4));
        v = fmaxf(v, __shfl_xor_sync(0xffffffffu, v, 2));
        v = fmaxf(v, __shfl_xor_sync(0xffffffffu, v, 1));
        f[o] = v;
    }
}

__global__ __launch_bounds__(256) void mlp_kernel(
    const float* __restrict__ w1a, const float* __restrict__ g1a, const float* __restrict__ b1a,
    const float* __restrict__ w1b, const float* __restrict__ g1b, const float* __restrict__ b1b,
    const float* __restrict__ w2a, const float* __restrict__ g2a, const float* __restrict__ b2a,
    const float* __restrict__ w2b, const float* __restrict__ g2b, const float* __restrict__ b2b,
    const float* __restrict__ b3,
    float* __restrict__ out)
{
    __shared__ float s_wa1[16 * 8], s_wa2[16 * 8];      // rows padded to 8
    __shared__ float s_wb1[32 * 16], s_wb2[32 * 16];
    __shared__ float s_sc1a[16], s_bi1a[16], s_sc2a[16], s_bi2a[16];
    __shared__ float s_sc1b[32], s_bi1b[32], s_sc2b[32], s_bi2b[32];

    const int tid = threadIdx.x;
    if (tid < 128) {
        const int o = tid >> 3, cc = tid & 7;
        s_wa1[tid] = (cc < 6) ? w1a[o * 6 + cc] : 0.0f;
        s_wa2[tid] = (cc < 6) ? w2a[o * 6 + cc] : 0.0f;
    }
    for (int i = tid; i < 512; i += 256) { s_wb1[i] = w1b[i]; s_wb2[i] = w2b[i]; }
    if (tid < 16) {
        s_sc1a[tid] = g1a[tid] * INVC; s_bi1a[tid] = b1a[tid];
        s_sc2a[tid] = g2a[tid] * INVC; s_bi2a[tid] = b2a[tid];
    } else if (tid < 48) {
        const int i = tid - 16;
        s_sc1b[i] = g1b[i] * INVC; s_bi1b[i] = b1b[i];
        s_sc2b[i] = g2b[i] * INVC; s_bi2b[i] = b2b[i];
    }

    const int lane = tid & 31;
    const int wid  = tid >> 5;
    const int q    = blockIdx.x * 8 + wid;
    int b;
    const int fi = query_flat_index(q, b);

    const float4* __restrict__ P4 = g_pts4 + (size_t)b * NPTS;
    const float4 qp = __ldg(P4 + fi);

    const int* lst = g_lists + q * 96;
    const int i0 = __ldg(lst + lane);
    const int i1 = __ldg(lst + NS1 + lane);
    const int i2 = __ldg(lst + NS1 + 32 + lane);
    const float4 n0 = __ldg(P4 + i0);
    const float4 n1 = __ldg(P4 + i1);
    const float4 n2 = __ldg(P4 + i2);

    __syncthreads();

    float f1[32], f2[32];
#pragma unroll
    for (int o = 0; o < 32; o++) { f1[o] = 0.0f; f2[o] = 0.0f; }

    mlp_point1(n0.x, n0.y, n0.z, qp.x, qp.y, qp.z,
               (const float4*)s_wa1, s_sc1a, s_bi1a,
               (const float4*)s_wb1, s_sc1b, s_bi1b, f1);
    mlp_point2(n1.x, n1.y, n1.z, n2.x, n2.y, n2.z, qp.x, qp.y, qp.z,
               (const float4*)s_wa2, s_sc2a, s_bi2a,
               (const float4*)s_wb2, s_sc2b, s_bi2b, f2);
    warp_max32(f1);
    warp_max32(f2);

    float acc0 = __ldg(b3 + lane +  0);
    float acc1 = __ldg(b3 + lane + 32);
    float acc2 = __ldg(b3 + lane + 64);
    float acc3 = __ldg(b3 + lane + 96);
#pragma unroll
    for (int c = 0; c < 32; c++) {
        const float4 w = __ldg(g_w3t4 + c * 32 + lane);
        acc0 = fmaf(f1[c], w.x, acc0);
        acc1 = fmaf(f1[c], w.y, acc1);
        acc2 = fmaf(f1[c], w.z, acc2);
        acc3 = fmaf(f1[c], w.w, acc3);
    }
#pragma unroll
    for (int c = 0; c < 32; c++) {
        const float4 w = __ldg(g_w3t4 + (c + 32) * 32 + lane);
        acc0 = fmaf(f2[c], w.x, acc0);
        acc1 = fmaf(f2[c], w.y, acc1);
        acc2 = fmaf(f2[c], w.z, acc2);
        acc3 = fmaf(f2[c], w.w, acc3);
    }
    const size_t ob = (size_t)q * NOUT;
    out[ob + lane +  0] = acc0;
    out[ob + lane + 32] = acc1;
    out[ob + lane + 64] = acc2;
    out[ob + lane + 96] = acc3;
}

extern "C" void kernel_launch(void* const* d_in, const int* in_sizes, int n_in,
                              void* d_out, int out_size) {
    const float* pts = (const float*)d_in[0];
    const float* w1a = (const float*)d_in[1];
    const float* g1a = (const float*)d_in[2];
    const float* b1a = (const float*)d_in[3];
    const float* w1b = (const float*)d_in[4];
    const float* g1b = (const float*)d_in[5];
    const float* b1b = (const float*)d_in[6];
    const float* w2a = (const float*)d_in[7];
    const float* g2a = (const float*)d_in[8];
    const float* b2a = (const float*)d_in[9];
    const float* w2b = (const float*)d_in[10];
    const float* g2b = (const float*)d_in[11];
    const float* b2b = (const float*)d_in[12];
    const float* w3  = (const float*)d_in[13];
    const float* b3  = (const float*)d_in[14];
    float* out = (float*)d_out;

    prep_kernel<<<NBATCH * NPTS / 256 + 8, 256>>>(pts, w3);
    scan1_kernel<<<NBATCH * NQ / 8, 256>>>();
    scan2_kernel<<<NBATCH * NQ, 256>>>();
    mlp_kernel<<<NBATCH * NQ / 8, 256>>>(w1a, g1a, b1a, w1b, g1b, b1b,
                                         w2a, g2a, b2a, w2b, g2b, b2b, b3, out);
}